// round 16
// baseline (speedup 1.0000x reference)
#include <cuda_runtime.h>
#include <cuda_fp16.h>
#include <cstdint>
#include <cstddef>

// Problem constants
#define Bsz 4
#define NQ  512
#define NK  2048
#define CDIM 1024
#define NHEADS 16
#define HDIM 64

// ---------------------------------------------------------------------------
// Scratch (device globals — no allocation allowed). All fp16.
// ---------------------------------------------------------------------------
__device__ __half g_inq[(size_t)Bsz * NQ * CDIM];
__device__ __half g_ink[(size_t)Bsz * NK * CDIM];
__device__ __half g_inv[(size_t)Bsz * NK * CDIM];
__device__ __half g_w[(size_t)4 * CDIM * CDIM];   // Wq,Wk,Wv,Wp (single fp16)
__device__ __half g_q[(size_t)Bsz * NQ * CDIM];
__device__ __half g_k[(size_t)Bsz * NK * CDIM];
__device__ __half g_v[(size_t)Bsz * NK * CDIM];
__device__ __half g_o[(size_t)Bsz * NQ * CDIM];

// ---------------------------------------------------------------------------
// Common helpers
// ---------------------------------------------------------------------------
__device__ __forceinline__ uint32_t smem_u32(const void* p) {
    uint32_t a;
    asm("{ .reg .u64 t; cvta.to.shared.u64 t, %1; cvt.u32.u64 %0, t; }"
        : "=r"(a) : "l"(p));
    return a;
}

__device__ __forceinline__ void cp16(uint32_t dst, const void* src) {
    asm volatile("cp.async.cg.shared.global [%0], [%1], 16;"
                 :: "r"(dst), "l"(src) : "memory");
}

__device__ __forceinline__ void ldm_x4(uint32_t* r, uint32_t addr) {
    asm volatile("ldmatrix.sync.aligned.m8n8.x4.shared.b16 {%0,%1,%2,%3}, [%4];"
                 : "=r"(r[0]), "=r"(r[1]), "=r"(r[2]), "=r"(r[3]) : "r"(addr));
}

__device__ __forceinline__ void ldm_x4_t(uint32_t* r, uint32_t addr) {
    asm volatile("ldmatrix.sync.aligned.m8n8.x4.trans.shared.b16 {%0,%1,%2,%3}, [%4];"
                 : "=r"(r[0]), "=r"(r[1]), "=r"(r[2]), "=r"(r[3]) : "r"(addr));
}

__device__ __forceinline__ void mma_f16(float* c, const uint32_t* a,
                                        uint32_t b0, uint32_t b1) {
    asm volatile(
        "mma.sync.aligned.m16n8k16.row.col.f32.f16.f16.f32 "
        "{%0,%1,%2,%3}, {%4,%5,%6,%7}, {%8,%9}, {%0,%1,%2,%3};"
        : "+f"(c[0]), "+f"(c[1]), "+f"(c[2]), "+f"(c[3])
        : "r"(a[0]), "r"(a[1]), "r"(a[2]), "r"(a[3]), "r"(b0), "r"(b1));
}

__device__ __forceinline__ uint32_t pack_h2(float a, float b) {
    __half2 t = __floats2half2_rn(a, b);
    return *(uint32_t*)&t;
}

// ---------------------------------------------------------------------------
// Fused convert kernel: q,k,v,W* fp32 -> fp16.
// ---------------------------------------------------------------------------
#define QN4 ((Bsz * NQ * CDIM) / 4)      // 524288
#define KN4 ((Bsz * NK * CDIM) / 4)      // 2097152
#define WN4 ((CDIM * CDIM) / 4)          // 262144
#define SPLIT_TOTAL (QN4 + 2 * KN4 + 4 * WN4)  // 5767168

__global__ void __launch_bounds__(256)
split_all_kernel(const float4* __restrict__ q, const float4* __restrict__ k,
                 const float4* __restrict__ v, const float4* __restrict__ wq,
                 const float4* __restrict__ wk, const float4* __restrict__ wv,
                 const float4* __restrict__ wp)
{
    int base = (blockIdx.x * blockDim.x + threadIdx.x) * 2;
#pragma unroll
    for (int e = 0; e < 2; e++) {
        int idx = base + e;
        const float4* src;
        __half2* dst;
        int off;
        if (idx < QN4) { src = q; off = idx; dst = (__half2*)g_inq; }
        else if (idx < QN4 + KN4) { src = k; off = idx - QN4; dst = (__half2*)g_ink; }
        else if (idx < QN4 + 2 * KN4) { src = v; off = idx - QN4 - KN4; dst = (__half2*)g_inv; }
        else {
            int widx = idx - QN4 - 2 * KN4;
            int seg = widx / WN4;
            off = widx - seg * WN4;
            src = (seg == 0) ? wq : (seg == 1) ? wk : (seg == 2) ? wv : wp;
            dst = (__half2*)(g_w + (size_t)seg * CDIM * CDIM);
        }
        float4 a = src[off];
        dst[off * 2 + 0] = __floats2half2_rn(a.x, a.y);
        dst[off * 2 + 1] = __floats2half2_rn(a.z, a.w);
    }
}

// ---------------------------------------------------------------------------
// qkv GEMM: 256x128 tiles, 512 threads (16 warps as 8 wm x 2 wn,
// warp tile 32x64), BK=64 (144B pitch), 2-stage pipeline.
// cp16/mma = 3 (vs 4 at 128x128).
// ---------------------------------------------------------------------------
#define PITCH_G 144
#define QKV_TILE_A (256 * PITCH_G)       // 36864
#define QKV_TILE_W (128 * PITCH_G)       // 18432
#define QKV_STAGE  (QKV_TILE_A + QKV_TILE_W)
#define GM_SMEM    (2 * QKV_STAGE)       // 110592

__device__ __forceinline__ void qkv_load_stage(const __half* __restrict__ A,
                                               const __half* __restrict__ W,
                                               int m0, int n0, int c,
                                               uint32_t sb, int tid)
{
    uint32_t st = sb + (c & 1) * QKV_STAGE;
    int k0 = c * 64;
    // A: 256 rows x 8 chunks = 2048 cp16 over 512 threads
#pragma unroll
    for (int i = 0; i < 4; i++) {
        int idx = tid + i * 512;
        int r  = idx >> 3;
        int ch = idx & 7;
        cp16(st + r * PITCH_G + ch * 16,
             A + (size_t)(m0 + r) * CDIM + k0 + ch * 8);
    }
    // W: 128 rows x 8 chunks = 1024 cp16
#pragma unroll
    for (int i = 0; i < 2; i++) {
        int idx = tid + i * 512;
        int r  = idx >> 3;
        int ch = idx & 7;
        cp16(st + QKV_TILE_A + r * PITCH_G + ch * 16,
             W + (size_t)(n0 + r) * CDIM + k0 + ch * 8);
    }
    asm volatile("cp.async.commit_group;" ::: "memory");
}

__device__ __forceinline__ void qkv_mainloop(
    const __half* __restrict__ A, const __half* __restrict__ W,
    int m0, int n0, uint32_t sb, int tid, float acc[2][8][4])
{
    const int lane = tid & 31;
    const int warp = tid >> 5;        // 0..15
    const int wm   = warp >> 1;       // 0..7
    const int wn   = warp & 1;        // 0..1

    const int arow = wm * 32 + ((lane >> 3) & 1) * 8 + (lane & 7);
    const int acol = (lane >> 4) * 8;
    const int brow = wn * 64 + ((lane >> 4) & 1) * 8 + (lane & 7);
    const int bcol = ((lane >> 3) & 1) * 8;

    qkv_load_stage(A, W, m0, n0, 0, sb, tid);

    const int NCHUNK = CDIM / 64;   // 16
    for (int c = 0; c < NCHUNK; c++) {
        asm volatile("cp.async.wait_group 0;" ::: "memory");
        __syncthreads();

        const uint32_t stg = sb + (c & 1) * QKV_STAGE;
        const uint32_t aB  = stg;
        const uint32_t wB  = stg + QKV_TILE_A;

#pragma unroll
        for (int s = 0; s < 4; s++) {
            const int kk = s * 16;
            uint32_t Af[2][4], Wf[4][4];
#pragma unroll
            for (int mi = 0; mi < 2; mi++)
                ldm_x4(Af[mi], aB + (uint32_t)((arow + mi * 16) * PITCH_G
                                               + (kk + acol) * 2));
#pragma unroll
            for (int nj = 0; nj < 4; nj++)
                ldm_x4(Wf[nj], wB + (uint32_t)((brow + nj * 16) * PITCH_G
                                               + (kk + bcol) * 2));
            if (s == 0 && c + 1 < NCHUNK)
                qkv_load_stage(A, W, m0, n0, c + 1, sb, tid);
#pragma unroll
            for (int mi = 0; mi < 2; mi++)
#pragma unroll
                for (int q = 0; q < 8; q++)
                    mma_f16(acc[mi][q], Af[mi],
                            Wf[q >> 1][(q & 1) * 2], Wf[q >> 1][(q & 1) * 2 + 1]);
        }
    }
}

// ---------------------------------------------------------------------------
// Fused QKV projection: 576 CTAs (256x128 tiles), 512 thr, 1 CTA/SM.
// ---------------------------------------------------------------------------
__global__ void __launch_bounds__(512, 1)
qkv_proj_kernel(const int* __restrict__ qpos, const int* __restrict__ kpos)
{
    extern __shared__ __align__(128) char smem[];
    const uint32_t sb = smem_u32(smem);
    const int tid  = threadIdx.x;
    const int lane = tid & 31;
    const int warp = tid >> 5;
    const int t    = blockIdx.x;

    // K: 256 tiles (8192/256 x 8), V: 256, Q: 64 (2048/256 x 8)
    int gemm, local;
    if (t < 256)      { gemm = 1; local = t; }
    else if (t < 512) { gemm = 2; local = t - 256; }
    else              { gemm = 0; local = t - 512; }
    const int m0 = (local >> 3) * 256;
    const int n0 = (local & 7) * 128;

    const __half *A, *W;
    if (gemm == 0)      { A = g_inq; W = g_w; }
    else if (gemm == 1) { A = g_ink; W = g_w + (size_t)CDIM * CDIM; }
    else                { A = g_inv; W = g_w + (size_t)2 * CDIM * CDIM; }

    float acc[2][8][4];
#pragma unroll
    for (int mi = 0; mi < 2; mi++)
#pragma unroll
        for (int q = 0; q < 8; q++)
#pragma unroll
            for (int u = 0; u < 4; u++) acc[mi][q][u] = 0.f;

    qkv_mainloop(A, W, m0, n0, sb, tid, acc);

    const int wm = warp >> 1;
    const int wn = warp & 1;
    const int er = m0 + wm * 32 + (lane >> 2);
    const int ec = n0 + wn * 64 + (lane & 3) * 2;

    if (gemm == 2) {
#pragma unroll
        for (int mi = 0; mi < 2; mi++) {
#pragma unroll
            for (int q = 0; q < 8; q++) {
                size_t off0 = (size_t)(er + mi * 16) * CDIM + ec + q * 8;
                size_t off1 = (size_t)(er + mi * 16 + 8) * CDIM + ec + q * 8;
                *(uint32_t*)(g_v + off0) = pack_h2(acc[mi][q][0], acc[mi][q][1]);
                *(uint32_t*)(g_v + off1) = pack_h2(acc[mi][q][2], acc[mi][q][3]);
            }
        }
        return;
    }

    const int* posarr = (gemm == 0) ? qpos : kpos;
    const float scale = (gemm == 0) ? 0.125f : 1.0f;
    __half* dst = (gemm == 0) ? g_q : g_k;
    const float kf = 13.2877123795494f / 32.0f;   // log2(10000)/32

    float invf[8];
#pragma unroll
    for (int qp = 0; qp < 4; qp++)
#pragma unroll
        for (int c = 0; c < 2; c++) {
            int j = (lane & 3) * 2 + qp * 8 + c;
            invf[qp * 2 + c] = exp2f(-(float)j * kf);
        }

#pragma unroll
    for (int mi = 0; mi < 2; mi++) {
#pragma unroll
        for (int tr = 0; tr < 2; tr++) {
            const int row = er + mi * 16 + tr * 8;
            const float p = (float)posarr[row];
#pragma unroll
            for (int qp = 0; qp < 4; qp++) {
                float y1[2], y2[2];
#pragma unroll
                for (int c = 0; c < 2; c++) {
                    float ang = p * invf[qp * 2 + c];
                    float s, co;
                    sincosf(ang, &s, &co);
                    float x1 = acc[mi][qp][tr * 2 + c];
                    float x2 = acc[mi][qp + 4][tr * 2 + c];
                    y1[c] = (x1 * co - x2 * s) * scale;
                    y2[c] = (x2 * co + x1 * s) * scale;
                }
                size_t offA = (size_t)row * CDIM + ec + qp * 8;
                size_t offB = (size_t)row * CDIM + ec + (qp + 4) * 8;
                *(uint32_t*)(dst + offA) = pack_h2(y1[0], y1[1]);
                *(uint32_t*)(dst + offB) = pack_h2(y2[0], y2[1]);
            }
        }
    }
}

// ---------------------------------------------------------------------------
// out_proj: 128x128 tiles, 512 thr (16 warps as 8 wm x 2 wn, warp 16x64),
// BK=32 (80B pitch), 3-stage. Grid 128 CTAs.
// ---------------------------------------------------------------------------
#define PITCH_B 80
#define OP_TILE_A (128 * PITCH_B)        // 10240
#define OP_TILE_W (128 * PITCH_B)        // 10240
#define OP_STAGE  (OP_TILE_A + OP_TILE_W)
#define GO_SMEM   (3 * OP_STAGE)         // 61440

__device__ __forceinline__ void op_load_stage(const __half* __restrict__ A,
                                              const __half* __restrict__ W,
                                              int m0, int n0, int c,
                                              uint32_t sb, int tid)
{
    uint32_t st = sb + (c % 3) * OP_STAGE;
    int k0 = c * 32;
    {   // A: 128 rows x 4 chunks = 512 cp16 (1/thread)
        int r = tid >> 2;
        int j = tid & 3;
        cp16(st + r * PITCH_B + j * 16,
             A + (size_t)(m0 + r) * CDIM + k0 + j * 8);
    }
    {   // W: 128 rows x 4 chunks = 512 cp16 (1/thread)
        int r = tid >> 2;
        int j = tid & 3;
        cp16(st + OP_TILE_A + r * PITCH_B + j * 16,
             W + (size_t)(n0 + r) * CDIM + k0 + j * 8);
    }
    asm volatile("cp.async.commit_group;" ::: "memory");
}

__global__ void __launch_bounds__(512, 1)
out_proj_kernel(const float* __restrict__ bias, float* __restrict__ Cout)
{
    extern __shared__ __align__(128) char smem[];
    const uint32_t sb = smem_u32(smem);
    const int tid  = threadIdx.x;
    const int lane = tid & 31;
    const int warp = tid >> 5;       // 0..15
    const int wm   = warp >> 1;      // 0..7
    const int wn   = warp & 1;
    const int m0   = blockIdx.y * 128;
    const int n0   = blockIdx.x * 128;

    float acc[8][4];
#pragma unroll
    for (int q = 0; q < 8; q++)
#pragma unroll
        for (int u = 0; u < 4; u++) acc[q][u] = 0.f;

    const int arow = wm * 16 + ((lane >> 3) & 1) * 8 + (lane & 7);
    const int acol = (lane >> 4) * 8;
    const int brow = wn * 64 + ((lane >> 4) & 1) * 8 + (lane & 7);
    const int bcol = ((lane >> 3) & 1) * 8;

    const __half* A = g_o;
    const __half* W = g_w + (size_t)3 * CDIM * CDIM;

    op_load_stage(A, W, m0, n0, 0, sb, tid);
    op_load_stage(A, W, m0, n0, 1, sb, tid);

    const int NCHUNK = CDIM / 32;   // 32
    for (int c = 0; c < NCHUNK; c++) {
        asm volatile("cp.async.wait_group 1;" ::: "memory");
        __syncthreads();
        if (c + 2 < NCHUNK) op_load_stage(A, W, m0, n0, c + 2, sb, tid);

        const uint32_t stg = sb + (c % 3) * OP_STAGE;
        const uint32_t aB  = stg;
        const uint32_t wB  = stg + OP_TILE_A;

#pragma unroll
        for (int s = 0; s < 2; s++) {
            const int kk = s * 16;
            uint32_t Af[4], Wf[4][4];
            ldm_x4(Af, aB + (uint32_t)(arow * PITCH_B + (kk + acol) * 2));
#pragma unroll
            for (int nj = 0; nj < 4; nj++)
                ldm_x4(Wf[nj], wB + (uint32_t)((brow + nj * 16) * PITCH_B
                                               + (kk + bcol) * 2));
#pragma unroll
            for (int q = 0; q < 8; q++)
                mma_f16(acc[q], Af,
                        Wf[q >> 1][(q & 1) * 2], Wf[q >> 1][(q & 1) * 2 + 1]);
        }
    }

    const int er = m0 + wm * 16 + (lane >> 2);
    const int ec = n0 + wn * 64 + (lane & 3) * 2;
#pragma unroll
    for (int q = 0; q < 8; q++) {
        float b0 = bias[ec + q * 8];
        float b1 = bias[ec + q * 8 + 1];
        float2 v0 = { acc[q][0] + b0, acc[q][1] + b1 };
        float2 v1 = { acc[q][2] + b0, acc[q][3] + b1 };
        *(float2*)&Cout[(size_t)er * CDIM + ec + q * 8]       = v0;
        *(float2*)&Cout[(size_t)(er + 8) * CDIM + ec + q * 8] = v1;
    }
}

// ---------------------------------------------------------------------------
// Flash attention (R15): 256 threads, 128 q-rows/CTA, 64-key tiles, h2exp2,
// 5-stage cp.async ring, two tiles per __syncthreads, 2 CTAs/SM.
// ---------------------------------------------------------------------------
#define ATK 64
#define KV_PITCH 144
#define KV_TILE  (ATK * KV_PITCH)       // 9216
#define AT_STAGE (2 * KV_TILE)          // 18432 (K + V)
#define AT_STAGES 5
#define AT_SMEM  (AT_STAGES * AT_STAGE) // 92160

__device__ __forceinline__ void at_load_tile(const __half* __restrict__ g,
                                             size_t gbase, uint32_t sbase, int tid)
{
#pragma unroll
    for (int i = 0; i < 2; i++) {
        int idx = tid + i * 256;
        int rr = idx >> 3;
        int ch = idx & 7;
        cp16(sbase + rr * KV_PITCH + ch * 16,
             g + gbase + (size_t)rr * CDIM + ch * 8);
    }
}

__device__ __forceinline__ void at_load_stage(size_t kgbase, int t,
                                              uint32_t sb, int tid)
{
    uint32_t st = sb + (t % AT_STAGES) * AT_STAGE;
    size_t gb = kgbase + (size_t)t * ATK * CDIM;
    at_load_tile(g_k, gb, st, tid);
    at_load_tile(g_v, gb, st + KV_TILE, tid);
    asm volatile("cp.async.commit_group;" ::: "memory");
}

__global__ void __launch_bounds__(256, 2)
attn_mma_kernel()
{
    extern __shared__ __align__(128) char smem[];
    const uint32_t sb = smem_u32(smem);
    const int tid  = threadIdx.x;
    const int lane = tid & 31;
    const int warp = tid >> 5;        // 0..7
    const int m0   = blockIdx.x * 128;
    const int h    = blockIdx.y;
    const int b    = blockIdx.z;

    const int r  = lane >> 2;
    const int c2 = (lane & 3) * 2;

    uint32_t Qf[4][4];
    {
        size_t qbase = ((size_t)(b * NQ + m0 + warp * 16)) * CDIM + h * HDIM;
#pragma unroll
        for (int ks = 0; ks < 4; ks++) {
            int col = ks * 16 + c2;
            Qf[ks][0] = *(const uint32_t*)(g_q + qbase + (size_t)r * CDIM + col);
            Qf[ks][1] = *(const uint32_t*)(g_q + qbase + (size_t)(r + 8) * CDIM + col);
            Qf[ks][2] = *(const uint32_t*)(g_q + qbase + (size_t)r * CDIM + col + 8);
            Qf[ks][3] = *(const uint32_t*)(g_q + qbase + (size_t)(r + 8) * CDIM + col + 8);
        }
    }

    const size_t kgbase = ((size_t)(b * NK)) * CDIM + h * HDIM;

    at_load_stage(kgbase, 0, sb, tid);
    at_load_stage(kgbase, 1, sb, tid);
    at_load_stage(kgbase, 2, sb, tid);

    float m[2] = { -1e30f, -1e30f };
    float l[2] = { 0.f, 0.f };
    float o[8][4];
#pragma unroll
    for (int nb = 0; nb < 8; nb++)
#pragma unroll
        for (int u = 0; u < 4; u++) o[nb][u] = 0.f;

    const int krow_off = ((lane >> 4) & 1) * 8 + (lane & 7);
    const int kcol_off = ((lane >> 3) & 1) * 16;
    const int vrow_off = (lane & 7) + ((lane >> 3) & 1) * 8;
    const int vcol_off = (lane >> 4) * 16;
    const float L2E = 1.44269504f;

    const int NT = NK / ATK;   // 32
    for (int t = 0; t < NT; t += 2) {
        asm volatile("cp.async.wait_group 1;" ::: "memory");
        __syncthreads();
        if (t + 3 < NT) at_load_stage(kgbase, t + 3, sb, tid);
        if (t + 4 < NT) at_load_stage(kgbase, t + 4, sb, tid);

#pragma unroll
        for (int u = 0; u < 2; u++) {
            const int tt = t + u;
            const uint32_t stg = sb + (tt % AT_STAGES) * AT_STAGE;
            const uint32_t kB  = stg;
            const uint32_t vB  = stg + KV_TILE;

            float sc[8][4];
#pragma unroll
            for (int nb = 0; nb < 8; nb++)
#pragma unroll
                for (int uu = 0; uu < 4; uu++) sc[nb][uu] = 0.f;

#pragma unroll
            for (int ks = 0; ks < 4; ks++) {
                uint32_t kf4[4][4];
#pragma unroll
                for (int nj = 0; nj < 4; nj++)
                    ldm_x4(kf4[nj], kB + (uint32_t)((nj * 16 + krow_off) * KV_PITCH
                                                    + ks * 32 + kcol_off));
#pragma unroll
                for (int nj = 0; nj < 4; nj++)
#pragma unroll
                    for (int nb = 0; nb < 2; nb++)
                        mma_f16(sc[nj * 2 + nb], Qf[ks],
                                kf4[nj][nb * 2], kf4[nj][nb * 2 + 1]);
            }

            uint32_t ph[8][2];
#pragma unroll
            for (int i = 0; i < 2; i++) {
                float mx = sc[0][2 * i];
#pragma unroll
                for (int nb = 0; nb < 8; nb++)
                    mx = fmaxf(mx, fmaxf(sc[nb][2 * i], sc[nb][2 * i + 1]));
                mx = fmaxf(mx, __shfl_xor_sync(0xFFFFFFFFu, mx, 1));
                mx = fmaxf(mx, __shfl_xor_sync(0xFFFFFFFFu, mx, 2));
                float mn = fmaxf(m[i], mx);
                float corr = exp2f((m[i] - mn) * L2E);
                m[i] = mn;
                float mnL = mn * L2E;
                float ls = 0.f;
#pragma unroll
                for (int nb = 0; nb < 8; nb++) {
                    float x0 = fmaf(sc[nb][2 * i], L2E, -mnL);
                    float x1 = fmaf(sc[nb][2 * i + 1], L2E, -mnL);
                    __half2 xh = __floats2half2_rn(x0, x1);
                    __half2 p  = h2exp2(xh);
                    ph[nb][i] = *(uint32_t*)&p;
                    float2 pf = __half22float2(p);
                    ls += pf.x + pf.y;
                }
                l[i] = l[i] * corr + ls;
#pragma unroll
                for (int nb = 0; nb < 8; nb++) {
                    o[nb][2 * i]     *= corr;
                    o[nb][2 * i + 1] *= corr;
                }
            }

#pragma unroll
            for (int j = 0; j < 4; j++) {
                uint32_t Pf[4] = { ph[2 * j][0], ph[2 * j][1],
                                   ph[2 * j + 1][0], ph[2 * j + 1][1] };
                uint32_t vf[4][4];
#pragma unroll
                for (int g = 0; g < 4; g++)
                    ldm_x4_t(vf[g], vB + (uint32_t)((j * 16 + vrow_off) * KV_PITCH
                                                    + g * 32 + vcol_off));
#pragma unroll
                for (int g = 0; g < 4; g++)
#pragma unroll
                    for (int nb = 0; nb < 2; nb++)
                        mma_f16(o[g * 2 + nb], Pf,
                                vf[g][nb * 2], vf[g][nb * 2 + 1]);
            }
        }
    }

    float inv[2];
#pragma unroll
    for (int i = 0; i < 2; i++) {
        float lt = l[i];
        lt += __shfl_xor_sync(0xFFFFFFFFu, lt, 1);
        lt += __shfl_xor_sync(0xFFFFFFFFu, lt, 2);
        inv[i] = 1.f / lt;
    }
    size_t obase = ((size_t)(b * NQ + m0 + warp * 16)) * CDIM + h * HDIM;
#pragma unroll
    for (int nb = 0; nb < 8; nb++) {
#pragma unroll
        for (int i = 0; i < 2; i++) {
            float x0 = o[nb][2 * i] * inv[i];
            float x1 = o[nb][2 * i + 1] * inv[i];
            size_t off = obase + (size_t)(r + i * 8) * CDIM + nb * 8 + c2;
            *(uint32_t*)(g_o + off) = pack_h2(x0, x1);
        }
    }
}

// ---------------------------------------------------------------------------
// Launcher
// ---------------------------------------------------------------------------
extern "C" void kernel_launch(void* const* d_in, const int* in_sizes, int n_in,
                              void* d_out, int out_size)
{
    const float* query = (const float*)d_in[0];
    const float* key   = (const float*)d_in[1];
    const float* value = (const float*)d_in[2];
    const int*   qpos  = (const int*)  d_in[3];
    const int*   kpos  = (const int*)  d_in[4];
    const float* Wq    = (const float*)d_in[5];
    const float* Wk    = (const float*)d_in[6];
    const float* Wv    = (const float*)d_in[7];
    const float* Wp    = (const float*)d_in[8];
    const float* bp    = (const float*)d_in[9];
    float* out = (float*)d_out;

    cudaFuncSetAttribute(qkv_proj_kernel,
                         cudaFuncAttributeMaxDynamicSharedMemorySize, GM_SMEM);
    cudaFuncSetAttribute(out_proj_kernel,
                         cudaFuncAttributeMaxDynamicSharedMemorySize, GO_SMEM);
    cudaFuncSetAttribute(attn_mma_kernel,
                         cudaFuncAttributeMaxDynamicSharedMemorySize, AT_SMEM);

    split_all_kernel<<<SPLIT_TOTAL / 512, 256>>>(
        (const float4*)query, (const float4*)key, (const float4*)value,
        (const float4*)Wq, (const float4*)Wk, (const float4*)Wv, (const float4*)Wp);

    qkv_proj_kernel<<<576, 512, GM_SMEM>>>(qpos, kpos);

    attn_mma_kernel<<<dim3(NQ / 128, NHEADS, Bsz), 256, AT_SMEM>>>();

    out_proj_kernel<<<dim3(CDIM / 128, (Bsz * NQ) / 128), 512, GO_SMEM>>>(bp, out);
}

// round 17
// speedup vs baseline: 1.0317x; 1.0317x over previous
#include <cuda_runtime.h>
#include <cuda_fp16.h>
#include <cstdint>
#include <cstddef>

// Problem constants
#define Bsz 4
#define NQ  512
#define NK  2048
#define CDIM 1024
#define NHEADS 16
#define HDIM 64

// ---------------------------------------------------------------------------
// Scratch (device globals — no allocation allowed). All fp16.
// ---------------------------------------------------------------------------
__device__ __half g_inq[(size_t)Bsz * NQ * CDIM];
__device__ __half g_ink[(size_t)Bsz * NK * CDIM];
__device__ __half g_inv[(size_t)Bsz * NK * CDIM];
__device__ __half g_w[(size_t)4 * CDIM * CDIM];   // Wq,Wk,Wv,Wp (single fp16)
__device__ __half g_q[(size_t)Bsz * NQ * CDIM];
__device__ __half g_k[(size_t)Bsz * NK * CDIM];
__device__ __half g_v[(size_t)Bsz * NK * CDIM];
__device__ __half g_o[(size_t)Bsz * NQ * CDIM];

// ---------------------------------------------------------------------------
// Common helpers
// ---------------------------------------------------------------------------
__device__ __forceinline__ uint32_t smem_u32(const void* p) {
    uint32_t a;
    asm("{ .reg .u64 t; cvta.to.shared.u64 t, %1; cvt.u32.u64 %0, t; }"
        : "=r"(a) : "l"(p));
    return a;
}

__device__ __forceinline__ void cp16(uint32_t dst, const void* src) {
    asm volatile("cp.async.cg.shared.global [%0], [%1], 16;"
                 :: "r"(dst), "l"(src) : "memory");
}

__device__ __forceinline__ void ldm_x4(uint32_t* r, uint32_t addr) {
    asm volatile("ldmatrix.sync.aligned.m8n8.x4.shared.b16 {%0,%1,%2,%3}, [%4];"
                 : "=r"(r[0]), "=r"(r[1]), "=r"(r[2]), "=r"(r[3]) : "r"(addr));
}

__device__ __forceinline__ void ldm_x4_t(uint32_t* r, uint32_t addr) {
    asm volatile("ldmatrix.sync.aligned.m8n8.x4.trans.shared.b16 {%0,%1,%2,%3}, [%4];"
                 : "=r"(r[0]), "=r"(r[1]), "=r"(r[2]), "=r"(r[3]) : "r"(addr));
}

__device__ __forceinline__ void mma_f16(float* c, const uint32_t* a,
                                        uint32_t b0, uint32_t b1) {
    asm volatile(
        "mma.sync.aligned.m16n8k16.row.col.f32.f16.f16.f32 "
        "{%0,%1,%2,%3}, {%4,%5,%6,%7}, {%8,%9}, {%0,%1,%2,%3};"
        : "+f"(c[0]), "+f"(c[1]), "+f"(c[2]), "+f"(c[3])
        : "r"(a[0]), "r"(a[1]), "r"(a[2]), "r"(a[3]), "r"(b0), "r"(b1));
}

__device__ __forceinline__ uint32_t pack_h2(float a, float b) {
    __half2 t = __floats2half2_rn(a, b);
    return *(uint32_t*)&t;
}

// ---------------------------------------------------------------------------
// Fused convert kernel: q,k,v,W* fp32 -> fp16.
// ---------------------------------------------------------------------------
#define QN4 ((Bsz * NQ * CDIM) / 4)      // 524288
#define KN4 ((Bsz * NK * CDIM) / 4)      // 2097152
#define WN4 ((CDIM * CDIM) / 4)          // 262144
#define SPLIT_TOTAL (QN4 + 2 * KN4 + 4 * WN4)  // 5767168

__global__ void __launch_bounds__(256)
split_all_kernel(const float4* __restrict__ q, const float4* __restrict__ k,
                 const float4* __restrict__ v, const float4* __restrict__ wq,
                 const float4* __restrict__ wk, const float4* __restrict__ wv,
                 const float4* __restrict__ wp)
{
    int base = (blockIdx.x * blockDim.x + threadIdx.x) * 2;
#pragma unroll
    for (int e = 0; e < 2; e++) {
        int idx = base + e;
        const float4* src;
        __half2* dst;
        int off;
        if (idx < QN4) { src = q; off = idx; dst = (__half2*)g_inq; }
        else if (idx < QN4 + KN4) { src = k; off = idx - QN4; dst = (__half2*)g_ink; }
        else if (idx < QN4 + 2 * KN4) { src = v; off = idx - QN4 - KN4; dst = (__half2*)g_inv; }
        else {
            int widx = idx - QN4 - 2 * KN4;
            int seg = widx / WN4;
            off = widx - seg * WN4;
            src = (seg == 0) ? wq : (seg == 1) ? wk : (seg == 2) ? wv : wp;
            dst = (__half2*)(g_w + (size_t)seg * CDIM * CDIM);
        }
        float4 a = src[off];
        dst[off * 2 + 0] = __floats2half2_rn(a.x, a.y);
        dst[off * 2 + 1] = __floats2half2_rn(a.z, a.w);
    }
}

// ---------------------------------------------------------------------------
// qkv GEMM (R14/R15 best): 128x128 tiles, 256 threads (8 warps as 4x2),
// BK=64 (144B pitch), 2-stage, 2 CTAs/SM.
// ---------------------------------------------------------------------------
#define PITCH_G 144
#define QKV_TILE_A (128 * PITCH_G)       // 18432
#define QKV_TILE_W (128 * PITCH_G)       // 18432
#define QKV_STAGE  (QKV_TILE_A + QKV_TILE_W)
#define GM_SMEM    (2 * QKV_STAGE)       // 73728

__device__ __forceinline__ void qkv_load_stage(const __half* __restrict__ A,
                                               const __half* __restrict__ W,
                                               int m0, int n0, int c,
                                               uint32_t sb, int tid)
{
    uint32_t st = sb + (c & 1) * QKV_STAGE;
    int k0 = c * 64;
#pragma unroll
    for (int i = 0; i < 4; i++) {        // A: 128 rows x 8 chunks
        int idx = tid + i * 256;
        int r  = idx >> 3;
        int ch = idx & 7;
        cp16(st + r * PITCH_G + ch * 16,
             A + (size_t)(m0 + r) * CDIM + k0 + ch * 8);
    }
#pragma unroll
    for (int i = 0; i < 4; i++) {        // W: 128 rows x 8 chunks
        int idx = tid + i * 256;
        int r  = idx >> 3;
        int ch = idx & 7;
        cp16(st + QKV_TILE_A + r * PITCH_G + ch * 16,
             W + (size_t)(n0 + r) * CDIM + k0 + ch * 8);
    }
    asm volatile("cp.async.commit_group;" ::: "memory");
}

__device__ __forceinline__ void qkv_mainloop(
    const __half* __restrict__ A, const __half* __restrict__ W,
    int m0, int n0, uint32_t sb, int tid, float acc[2][8][4])
{
    const int lane = tid & 31;
    const int warp = tid >> 5;
    const int wm   = warp >> 1;
    const int wn   = warp & 1;

    const int arow = wm * 32 + ((lane >> 3) & 1) * 8 + (lane & 7);
    const int acol = (lane >> 4) * 8;
    const int brow = wn * 64 + ((lane >> 4) & 1) * 8 + (lane & 7);
    const int bcol = ((lane >> 3) & 1) * 8;

    qkv_load_stage(A, W, m0, n0, 0, sb, tid);

    const int NCHUNK = CDIM / 64;   // 16
    for (int c = 0; c < NCHUNK; c++) {
        asm volatile("cp.async.wait_group 0;" ::: "memory");
        __syncthreads();

        const uint32_t stg = sb + (c & 1) * QKV_STAGE;
        const uint32_t aB  = stg;
        const uint32_t wB  = stg + QKV_TILE_A;

#pragma unroll
        for (int s = 0; s < 4; s++) {
            const int kk = s * 16;
            uint32_t Af[2][4], Wf[4][4];
#pragma unroll
            for (int mi = 0; mi < 2; mi++)
                ldm_x4(Af[mi], aB + (uint32_t)((arow + mi * 16) * PITCH_G
                                               + (kk + acol) * 2));
#pragma unroll
            for (int nj = 0; nj < 4; nj++)
                ldm_x4(Wf[nj], wB + (uint32_t)((brow + nj * 16) * PITCH_G
                                               + (kk + bcol) * 2));
            if (s == 0 && c + 1 < NCHUNK)
                qkv_load_stage(A, W, m0, n0, c + 1, sb, tid);
#pragma unroll
            for (int mi = 0; mi < 2; mi++)
#pragma unroll
                for (int q = 0; q < 8; q++)
                    mma_f16(acc[mi][q], Af[mi],
                            Wf[q >> 1][(q & 1) * 2], Wf[q >> 1][(q & 1) * 2 + 1]);
        }
    }
}

// ---------------------------------------------------------------------------
// Fused QKV projection: 1152 tiles (128x128), 256 thr, 2 CTAs/SM.
// ---------------------------------------------------------------------------
__global__ void __launch_bounds__(256, 2)
qkv_proj_kernel(const int* __restrict__ qpos, const int* __restrict__ kpos)
{
    extern __shared__ __align__(128) char smem[];
    const uint32_t sb = smem_u32(smem);
    const int tid  = threadIdx.x;
    const int lane = tid & 31;
    const int warp = tid >> 5;
    const int t    = blockIdx.x;

    int gemm, local;
    if (t < 512)       { gemm = 1; local = t; }
    else if (t < 1024) { gemm = 2; local = t - 512; }
    else               { gemm = 0; local = t - 1024; }
    const int m0 = (local >> 3) * 128;
    const int n0 = (local & 7) * 128;

    const __half *A, *W;
    if (gemm == 0)      { A = g_inq; W = g_w; }
    else if (gemm == 1) { A = g_ink; W = g_w + (size_t)CDIM * CDIM; }
    else                { A = g_inv; W = g_w + (size_t)2 * CDIM * CDIM; }

    float acc[2][8][4];
#pragma unroll
    for (int mi = 0; mi < 2; mi++)
#pragma unroll
        for (int q = 0; q < 8; q++)
#pragma unroll
            for (int u = 0; u < 4; u++) acc[mi][q][u] = 0.f;

    qkv_mainloop(A, W, m0, n0, sb, tid, acc);

    const int wm = warp >> 1;
    const int wn = warp & 1;
    const int er = m0 + wm * 32 + (lane >> 2);
    const int ec = n0 + wn * 64 + (lane & 3) * 2;

    if (gemm == 2) {
#pragma unroll
        for (int mi = 0; mi < 2; mi++) {
#pragma unroll
            for (int q = 0; q < 8; q++) {
                size_t off0 = (size_t)(er + mi * 16) * CDIM + ec + q * 8;
                size_t off1 = (size_t)(er + mi * 16 + 8) * CDIM + ec + q * 8;
                *(uint32_t*)(g_v + off0) = pack_h2(acc[mi][q][0], acc[mi][q][1]);
                *(uint32_t*)(g_v + off1) = pack_h2(acc[mi][q][2], acc[mi][q][3]);
            }
        }
        return;
    }

    const int* posarr = (gemm == 0) ? qpos : kpos;
    const float scale = (gemm == 0) ? 0.125f : 1.0f;
    __half* dst = (gemm == 0) ? g_q : g_k;
    const float kf = 13.2877123795494f / 32.0f;   // log2(10000)/32

    float invf[8];
#pragma unroll
    for (int qp = 0; qp < 4; qp++)
#pragma unroll
        for (int c = 0; c < 2; c++) {
            int j = (lane & 3) * 2 + qp * 8 + c;
            invf[qp * 2 + c] = exp2f(-(float)j * kf);
        }

#pragma unroll
    for (int mi = 0; mi < 2; mi++) {
#pragma unroll
        for (int tr = 0; tr < 2; tr++) {
            const int row = er + mi * 16 + tr * 8;
            const float p = (float)posarr[row];
#pragma unroll
            for (int qp = 0; qp < 4; qp++) {
                float y1[2], y2[2];
#pragma unroll
                for (int c = 0; c < 2; c++) {
                    float ang = p * invf[qp * 2 + c];
                    float s, co;
                    sincosf(ang, &s, &co);
                    float x1 = acc[mi][qp][tr * 2 + c];
                    float x2 = acc[mi][qp + 4][tr * 2 + c];
                    y1[c] = (x1 * co - x2 * s) * scale;
                    y2[c] = (x2 * co + x1 * s) * scale;
                }
                size_t offA = (size_t)row * CDIM + ec + qp * 8;
                size_t offB = (size_t)row * CDIM + ec + (qp + 4) * 8;
                *(uint32_t*)(dst + offA) = pack_h2(y1[0], y1[1]);
                *(uint32_t*)(dst + offB) = pack_h2(y2[0], y2[1]);
            }
        }
    }
}

// ---------------------------------------------------------------------------
// out_proj (R16 best): 128x128 tiles, 512 thr (16 warps as 8 wm x 2 wn,
// warp 16x64), BK=32 (80B pitch), 3-stage. Grid 128 CTAs.
// ---------------------------------------------------------------------------
#define PITCH_B 80
#define OP_TILE_A (128 * PITCH_B)        // 10240
#define OP_TILE_W (128 * PITCH_B)        // 10240
#define OP_STAGE  (OP_TILE_A + OP_TILE_W)
#define GO_SMEM   (3 * OP_STAGE)         // 61440

__device__ __forceinline__ void op_load_stage(const __half* __restrict__ A,
                                              const __half* __restrict__ W,
                                              int m0, int n0, int c,
                                              uint32_t sb, int tid)
{
    uint32_t st = sb + (c % 3) * OP_STAGE;
    int k0 = c * 32;
    {
        int r = tid >> 2;
        int j = tid & 3;
        cp16(st + r * PITCH_B + j * 16,
             A + (size_t)(m0 + r) * CDIM + k0 + j * 8);
    }
    {
        int r = tid >> 2;
        int j = tid & 3;
        cp16(st + OP_TILE_A + r * PITCH_B + j * 16,
             W + (size_t)(n0 + r) * CDIM + k0 + j * 8);
    }
    asm volatile("cp.async.commit_group;" ::: "memory");
}

__global__ void __launch_bounds__(512, 1)
out_proj_kernel(const float* __restrict__ bias, float* __restrict__ Cout)
{
    extern __shared__ __align__(128) char smem[];
    const uint32_t sb = smem_u32(smem);
    const int tid  = threadIdx.x;
    const int lane = tid & 31;
    const int warp = tid >> 5;       // 0..15
    const int wm   = warp >> 1;      // 0..7
    const int wn   = warp & 1;
    const int m0   = blockIdx.y * 128;
    const int n0   = blockIdx.x * 128;

    float acc[8][4];
#pragma unroll
    for (int q = 0; q < 8; q++)
#pragma unroll
        for (int u = 0; u < 4; u++) acc[q][u] = 0.f;

    const int arow = wm * 16 + ((lane >> 3) & 1) * 8 + (lane & 7);
    const int acol = (lane >> 4) * 8;
    const int brow = wn * 64 + ((lane >> 4) & 1) * 8 + (lane & 7);
    const int bcol = ((lane >> 3) & 1) * 8;

    const __half* A = g_o;
    const __half* W = g_w + (size_t)3 * CDIM * CDIM;

    op_load_stage(A, W, m0, n0, 0, sb, tid);
    op_load_stage(A, W, m0, n0, 1, sb, tid);

    const int NCHUNK = CDIM / 32;   // 32
    for (int c = 0; c < NCHUNK; c++) {
        asm volatile("cp.async.wait_group 1;" ::: "memory");
        __syncthreads();
        if (c + 2 < NCHUNK) op_load_stage(A, W, m0, n0, c + 2, sb, tid);

        const uint32_t stg = sb + (c % 3) * OP_STAGE;
        const uint32_t aB  = stg;
        const uint32_t wB  = stg + OP_TILE_A;

#pragma unroll
        for (int s = 0; s < 2; s++) {
            const int kk = s * 16;
            uint32_t Af[4], Wf[4][4];
            ldm_x4(Af, aB + (uint32_t)(arow * PITCH_B + (kk + acol) * 2));
#pragma unroll
            for (int nj = 0; nj < 4; nj++)
                ldm_x4(Wf[nj], wB + (uint32_t)((brow + nj * 16) * PITCH_B
                                               + (kk + bcol) * 2));
#pragma unroll
            for (int q = 0; q < 8; q++)
                mma_f16(acc[q], Af,
                        Wf[q >> 1][(q & 1) * 2], Wf[q >> 1][(q & 1) * 2 + 1]);
        }
    }

    const int er = m0 + wm * 16 + (lane >> 2);
    const int ec = n0 + wn * 64 + (lane & 3) * 2;
#pragma unroll
    for (int q = 0; q < 8; q++) {
        float b0 = bias[ec + q * 8];
        float b1 = bias[ec + q * 8 + 1];
        float2 v0 = { acc[q][0] + b0, acc[q][1] + b1 };
        float2 v1 = { acc[q][2] + b0, acc[q][3] + b1 };
        *(float2*)&Cout[(size_t)er * CDIM + ec + q * 8]       = v0;
        *(float2*)&Cout[(size_t)(er + 8) * CDIM + ec + q * 8] = v1;
    }
}

// ---------------------------------------------------------------------------
// Flash attention (R15 best): 256 threads, 128 q-rows/CTA, 64-key tiles,
// h2exp2 softmax, 5-stage cp.async ring, two tiles per sync, 2 CTAs/SM.
// ---------------------------------------------------------------------------
#define ATK 64
#define KV_PITCH 144
#define KV_TILE  (ATK * KV_PITCH)       // 9216
#define AT_STAGE (2 * KV_TILE)          // 18432 (K + V)
#define AT_STAGES 5
#define AT_SMEM  (AT_STAGES * AT_STAGE) // 92160

__device__ __forceinline__ void at_load_tile(const __half* __restrict__ g,
                                             size_t gbase, uint32_t sbase, int tid)
{
#pragma unroll
    for (int i = 0; i < 2; i++) {
        int idx = tid + i * 256;
        int rr = idx >> 3;
        int ch = idx & 7;
        cp16(sbase + rr * KV_PITCH + ch * 16,
             g + gbase + (size_t)rr * CDIM + ch * 8);
    }
}

__device__ __forceinline__ void at_load_stage(size_t kgbase, int t,
                                              uint32_t sb, int tid)
{
    uint32_t st = sb + (t % AT_STAGES) * AT_STAGE;
    size_t gb = kgbase + (size_t)t * ATK * CDIM;
    at_load_tile(g_k, gb, st, tid);
    at_load_tile(g_v, gb, st + KV_TILE, tid);
    asm volatile("cp.async.commit_group;" ::: "memory");
}

__global__ void __launch_bounds__(256, 2)
attn_mma_kernel()
{
    extern __shared__ __align__(128) char smem[];
    const uint32_t sb = smem_u32(smem);
    const int tid  = threadIdx.x;
    const int lane = tid & 31;
    const int warp = tid >> 5;        // 0..7
    const int m0   = blockIdx.x * 128;
    const int h    = blockIdx.y;
    const int b    = blockIdx.z;

    const int r  = lane >> 2;
    const int c2 = (lane & 3) * 2;

    uint32_t Qf[4][4];
    {
        size_t qbase = ((size_t)(b * NQ + m0 + warp * 16)) * CDIM + h * HDIM;
#pragma unroll
        for (int ks = 0; ks < 4; ks++) {
            int col = ks * 16 + c2;
            Qf[ks][0] = *(const uint32_t*)(g_q + qbase + (size_t)r * CDIM + col);
            Qf[ks][1] = *(const uint32_t*)(g_q + qbase + (size_t)(r + 8) * CDIM + col);
            Qf[ks][2] = *(const uint32_t*)(g_q + qbase + (size_t)r * CDIM + col + 8);
            Qf[ks][3] = *(const uint32_t*)(g_q + qbase + (size_t)(r + 8) * CDIM + col + 8);
        }
    }

    const size_t kgbase = ((size_t)(b * NK)) * CDIM + h * HDIM;

    at_load_stage(kgbase, 0, sb, tid);
    at_load_stage(kgbase, 1, sb, tid);
    at_load_stage(kgbase, 2, sb, tid);

    float m[2] = { -1e30f, -1e30f };
    float l[2] = { 0.f, 0.f };
    float o[8][4];
#pragma unroll
    for (int nb = 0; nb < 8; nb++)
#pragma unroll
        for (int u = 0; u < 4; u++) o[nb][u] = 0.f;

    const int krow_off = ((lane >> 4) & 1) * 8 + (lane & 7);
    const int kcol_off = ((lane >> 3) & 1) * 16;
    const int vrow_off = (lane & 7) + ((lane >> 3) & 1) * 8;
    const int vcol_off = (lane >> 4) * 16;
    const float L2E = 1.44269504f;

    const int NT = NK / ATK;   // 32
    for (int t = 0; t < NT; t += 2) {
        asm volatile("cp.async.wait_group 1;" ::: "memory");
        __syncthreads();
        if (t + 3 < NT) at_load_stage(kgbase, t + 3, sb, tid);
        if (t + 4 < NT) at_load_stage(kgbase, t + 4, sb, tid);

#pragma unroll
        for (int u = 0; u < 2; u++) {
            const int tt = t + u;
            const uint32_t stg = sb + (tt % AT_STAGES) * AT_STAGE;
            const uint32_t kB  = stg;
            const uint32_t vB  = stg + KV_TILE;

            float sc[8][4];
#pragma unroll
            for (int nb = 0; nb < 8; nb++)
#pragma unroll
                for (int uu = 0; uu < 4; uu++) sc[nb][uu] = 0.f;

#pragma unroll
            for (int ks = 0; ks < 4; ks++) {
                uint32_t kf4[4][4];
#pragma unroll
                for (int nj = 0; nj < 4; nj++)
                    ldm_x4(kf4[nj], kB + (uint32_t)((nj * 16 + krow_off) * KV_PITCH
                                                    + ks * 32 + kcol_off));
#pragma unroll
                for (int nj = 0; nj < 4; nj++)
#pragma unroll
                    for (int nb = 0; nb < 2; nb++)
                        mma_f16(sc[nj * 2 + nb], Qf[ks],
                                kf4[nj][nb * 2], kf4[nj][nb * 2 + 1]);
            }

            uint32_t ph[8][2];
#pragma unroll
            for (int i = 0; i < 2; i++) {
                float mx = sc[0][2 * i];
#pragma unroll
                for (int nb = 0; nb < 8; nb++)
                    mx = fmaxf(mx, fmaxf(sc[nb][2 * i], sc[nb][2 * i + 1]));
                mx = fmaxf(mx, __shfl_xor_sync(0xFFFFFFFFu, mx, 1));
                mx = fmaxf(mx, __shfl_xor_sync(0xFFFFFFFFu, mx, 2));
                float mn = fmaxf(m[i], mx);
                float corr = exp2f((m[i] - mn) * L2E);
                m[i] = mn;
                float mnL = mn * L2E;
                float ls = 0.f;
#pragma unroll
                for (int nb = 0; nb < 8; nb++) {
                    float x0 = fmaf(sc[nb][2 * i], L2E, -mnL);
                    float x1 = fmaf(sc[nb][2 * i + 1], L2E, -mnL);
                    __half2 xh = __floats2half2_rn(x0, x1);
                    __half2 p  = h2exp2(xh);
                    ph[nb][i] = *(uint32_t*)&p;
                    float2 pf = __half22float2(p);
                    ls += pf.x + pf.y;
                }
                l[i] = l[i] * corr + ls;
#pragma unroll
                for (int nb = 0; nb < 8; nb++) {
                    o[nb][2 * i]     *= corr;
                    o[nb][2 * i + 1] *= corr;
                }
            }

#pragma unroll
            for (int j = 0; j < 4; j++) {
                uint32_t Pf[4] = { ph[2 * j][0], ph[2 * j][1],
                                   ph[2 * j + 1][0], ph[2 * j + 1][1] };
                uint32_t vf[4][4];
#pragma unroll
                for (int g = 0; g < 4; g++)
                    ldm_x4_t(vf[g], vB + (uint32_t)((j * 16 + vrow_off) * KV_PITCH
                                                    + g * 32 + vcol_off));
#pragma unroll
                for (int g = 0; g < 4; g++)
#pragma unroll
                    for (int nb = 0; nb < 2; nb++)
                        mma_f16(o[g * 2 + nb], Pf,
                                vf[g][nb * 2], vf[g][nb * 2 + 1]);
            }
        }
    }

    float inv[2];
#pragma unroll
    for (int i = 0; i < 2; i++) {
        float lt = l[i];
        lt += __shfl_xor_sync(0xFFFFFFFFu, lt, 1);
        lt += __shfl_xor_sync(0xFFFFFFFFu, lt, 2);
        inv[i] = 1.f / lt;
    }
    size_t obase = ((size_t)(b * NQ + m0 + warp * 16)) * CDIM + h * HDIM;
#pragma unroll
    for (int nb = 0; nb < 8; nb++) {
#pragma unroll
        for (int i = 0; i < 2; i++) {
            float x0 = o[nb][2 * i] * inv[i];
            float x1 = o[nb][2 * i + 1] * inv[i];
            size_t off = obase + (size_t)(r + i * 8) * CDIM + nb * 8 + c2;
            *(uint32_t*)(g_o + off) = pack_h2(x0, x1);
        }
    }
}

// ---------------------------------------------------------------------------
// Launcher
// ---------------------------------------------------------------------------
extern "C" void kernel_launch(void* const* d_in, const int* in_sizes, int n_in,
                              void* d_out, int out_size)
{
    const float* query = (const float*)d_in[0];
    const float* key   = (const float*)d_in[1];
    const float* value = (const float*)d_in[2];
    const int*   qpos  = (const int*)  d_in[3];
    const int*   kpos  = (const int*)  d_in[4];
    const float* Wq    = (const float*)d_in[5];
    const float* Wk    = (const float*)d_in[6];
    const float* Wv    = (const float*)d_in[7];
    const float* Wp    = (const float*)d_in[8];
    const float* bp    = (const float*)d_in[9];
    float* out = (float*)d_out;

    cudaFuncSetAttribute(qkv_proj_kernel,
                         cudaFuncAttributeMaxDynamicSharedMemorySize, GM_SMEM);
    cudaFuncSetAttribute(out_proj_kernel,
                         cudaFuncAttributeMaxDynamicSharedMemorySize, GO_SMEM);
    cudaFuncSetAttribute(attn_mma_kernel,
                         cudaFuncAttributeMaxDynamicSharedMemorySize, AT_SMEM);

    split_all_kernel<<<SPLIT_TOTAL / 512, 256>>>(
        (const float4*)query, (const float4*)key, (const float4*)value,
        (const float4*)Wq, (const float4*)Wk, (const float4*)Wv, (const float4*)Wp);

    qkv_proj_kernel<<<1152, 256, GM_SMEM>>>(qpos, kpos);

    attn_mma_kernel<<<dim3(NQ / 128, NHEADS, Bsz), 256, AT_SMEM>>>();

    out_proj_kernel<<<dim3(CDIM / 128, (Bsz * NQ) / 128), 512, GO_SMEM>>>(bp, out);
}